// round 11
// baseline (speedup 1.0000x reference)
#include <cuda_runtime.h>
#include <cstdint>

#define NPAPER 60000
#define NAUTH  30000
#define NEC    300000
#define NEW_   150000
#define NEB    150000
#define HIDDEN 512
#define NCLS   153

// ---------------- scratch (device globals; no allocation allowed) ----------------
__device__ float g_ZP [(size_t)NPAPER * 1536];
__device__ float g_ZA [(size_t)NAUTH  * 1024];
__device__ float g_OP [(size_t)NPAPER * HIDDEN];
__device__ float g_OA [(size_t)NAUTH * HIDDEN];
__device__ float g_Ap [(size_t)NPAPER * 1024];   // tf32 layer-0 paper feats / classifier scratch
__device__ float g_Aa [(size_t)NAUTH  * 1024];
__device__ float g_Wp [(size_t)1024 * 1536];
__device__ float g_Wa [(size_t)1024 * 1024];
__device__ float g_lin[512 * 256];
__device__ float g_elc[NPAPER * 4];
__device__ float g_erc[NPAPER * 4];
__device__ float g_elw[NAUTH  * 4];
__device__ float g_erw[NPAPER * 4];
__device__ float g_elb[NPAPER * 4];
__device__ float g_erb[NAUTH  * 4];
__device__ float g_jp [NPAPER * 4];
__device__ float g_ja [NAUTH  * 4];
// CSR scratch
__device__ int g_cnt [NPAPER];
__device__ int g_offc[NPAPER + 1];
__device__ int g_offw[NPAPER + 1];
__device__ int g_offb[NAUTH + 1];
__device__ int g_eidc[NEC];
__device__ int g_eidw[NEW_];
__device__ int g_eidb[NEB];

// ---------------- helpers ----------------
__device__ __forceinline__ float rna_tf32(float f) {
    unsigned u;
    asm("cvt.rna.tf32.f32 %0, %1;" : "=r"(u) : "f"(f));
    return __uint_as_float(u);
}

__global__ void k_izero(int* __restrict__ p, int n) {
    int i = blockIdx.x * blockDim.x + threadIdx.x;
    int stride = gridDim.x * blockDim.x;
    for (; i < n; i += stride) p[i] = 0;
}

__global__ void k_cvt_tf32(const float* __restrict__ in, float* __restrict__ out, int n4) {
    int i = blockIdx.x * blockDim.x + threadIdx.x;
    int stride = gridDim.x * blockDim.x;
    for (; i < n4; i += stride) {
        float4 v = ((const float4*)in)[i];
        v.x = rna_tf32(v.x); v.y = rna_tf32(v.y);
        v.z = rna_tf32(v.z); v.w = rna_tf32(v.w);
        ((float4*)out)[i] = v;
    }
}

// pack weights W[(3,K,512)] relations [r0, r0+nrel) -> out[k][(q*512)+n], tf32
__global__ void k_pack_w(const float* __restrict__ W, float* __restrict__ out,
                         int K, int r0, int nrel) {
    int total = K * nrel * 128;
    int i = blockIdx.x * blockDim.x + threadIdx.x;
    int stride = gridDim.x * blockDim.x;
    for (; i < total; i += stride) {
        int n4 = i & 127;
        int kq = i >> 7;
        int q = kq % nrel, k = kq / nrel;
        float4 v = ((const float4*)(W + ((size_t)(r0 + q) * K + k) * 512))[n4];
        v.x = rna_tf32(v.x); v.y = rna_tf32(v.y);
        v.z = rna_tf32(v.z); v.w = rna_tf32(v.w);
        ((float4*)(out + ((size_t)k * nrel + q) * 512))[n4] = v;
    }
}

__global__ void k_pack_lin(const float* __restrict__ linW, float* __restrict__ out) {
    int i = blockIdx.x * blockDim.x + threadIdx.x;
    if (i >= 512 * 256) return;
    int k = i >> 8, c = i & 255;
    out[i] = (c < NCLS) ? rna_tf32(linW[k * NCLS + c]) : 0.0f;
}

__global__ void k_bias_out(const float* __restrict__ CO, const float* __restrict__ bias,
                           float* __restrict__ out, int M) {
    int i = blockIdx.x * blockDim.x + threadIdx.x;
    int stride = gridDim.x * blockDim.x;
    int total = M * NCLS;
    for (; i < total; i += stride) {
        int r = i / NCLS, c = i - r * NCLS;
        out[i] = CO[(size_t)r * 256 + c] + bias[c];
    }
}

// ---------------- CSR build ----------------
__global__ void k_hist(const int* __restrict__ dst, int E, int* __restrict__ cnt) {
    int e = blockIdx.x * blockDim.x + threadIdx.x;
    if (e < E) atomicAdd(&cnt[dst[e]], 1);
}

__global__ void k_scan(const int* __restrict__ cnt, int* __restrict__ off, int n) {
    __shared__ int sh[1024];
    int tid = threadIdx.x;
    int C = (n + 1023) / 1024;
    int b = tid * C;
    int sum = 0;
    for (int i = 0; i < C; i++)
        if (b + i < n) sum += cnt[b + i];
    sh[tid] = sum;
    __syncthreads();
    for (int d = 1; d < 1024; d <<= 1) {
        int t = 0;
        if (tid >= d) t = sh[tid - d];
        __syncthreads();
        if (tid >= d) sh[tid] += t;
        __syncthreads();
    }
    int run = sh[tid] - sum;
    for (int i = 0; i < C; i++) {
        if (b + i < n) { off[b + i] = run; run += cnt[b + i]; }
    }
    if (tid == 1023) off[n] = sh[1023];
}

__global__ void k_scatter(const int* __restrict__ dst, int E,
                          const int* __restrict__ off, int* __restrict__ cur,
                          int* __restrict__ eid) {
    int e = blockIdx.x * blockDim.x + threadIdx.x;
    if (e >= E) return;
    int d = dst[e];
    int p = off[d] + atomicAdd(&cur[d], 1);
    eid[p] = e;
}

// ---------------- TF32 tensor-core GEMM, 256x128 tile, 3-stage cp.async ----------------
// C[M,N] = A[M,K] @ B[K,N], row-major, N % 128 == 0, K % 16 == 0, inputs tf32-rounded.
// 8 warps as 4(m) x 2(n); warp tile 64x64 (mi=4, ni=8).
#define AS_STRIDE 20
#define BS_STRIDE 136
#define GSTAGES 3
#define SMEM_GEMM ((GSTAGES * 256 * AS_STRIDE + GSTAGES * 16 * BS_STRIDE) * 4)

__device__ __forceinline__ uint32_t smem_u32(const void* p) {
    uint32_t a;
    asm("{ .reg .u64 t; cvta.to.shared.u64 t, %1; cvt.u32.u64 %0, t; }" : "=r"(a) : "l"(p));
    return a;
}

__device__ __forceinline__ void cp16(uint32_t s, const float* g, bool v) {
    asm volatile("cp.async.cg.shared.global [%0], [%1], 16, %2;"
                 :: "r"(s), "l"(__cvta_generic_to_global(g)), "r"(v ? 16 : 0));
}

__device__ __forceinline__ void gemm_issue_tile(
    float* Asb, float* Bsb, int s,
    const float* __restrict__ A, const float* __restrict__ B,
    int bm, int bn, int M, int N, int K, int k0, int tid)
{
    int am = tid >> 2, ac4 = tid & 3;
    int bk = tid >> 5, bc4 = tid & 31;
    float* As = Asb + s * 256 * AS_STRIDE;
    float* Bs = Bsb + s * 16 * BS_STRIDE;
#pragma unroll
    for (int i = 0; i < 4; i++) {
        int m = am + i * 64;
        int mm = bm + m;
        int msafe = mm < M ? mm : (M - 1);
        cp16(smem_u32(As + m * AS_STRIDE + ac4 * 4),
             A + (size_t)msafe * K + k0 + ac4 * 4, mm < M);
    }
#pragma unroll
    for (int i = 0; i < 2; i++) {
        int kr = bk + i * 8;
        cp16(smem_u32(Bs + kr * BS_STRIDE + bc4 * 4),
             B + (size_t)(k0 + kr) * N + bn + bc4 * 4, true);
    }
    asm volatile("cp.async.commit_group;" ::: "memory");
}

__global__ __launch_bounds__(256) void k_tf32_gemm(
    const float* __restrict__ A, const float* __restrict__ B,
    float* __restrict__ C, int M, int N, int K)
{
    extern __shared__ float sm[];
    float* Asb = sm;
    float* Bsb = sm + GSTAGES * 256 * AS_STRIDE;

    int tid = threadIdx.x;
    int lane = tid & 31;
    int wid = tid >> 5;
    int warp_m = wid >> 1;   // 0..3 -> 64 rows each
    int warp_n = wid & 1;    // 0..1 -> 64 cols each
    int gr = lane >> 2;
    int gc = lane & 3;

    int bm = blockIdx.y * 256;
    int bn = blockIdx.x * 128;

    float acc[4][8][4];
#pragma unroll
    for (int mi = 0; mi < 4; mi++)
#pragma unroll
        for (int ni = 0; ni < 8; ni++)
#pragma unroll
            for (int j = 0; j < 4; j++) acc[mi][ni][j] = 0.0f;

    int nt = K >> 4;

    gemm_issue_tile(Asb, Bsb, 0, A, B, bm, bn, M, N, K, 0, tid);
    if (nt > 1)
        gemm_issue_tile(Asb, Bsb, 1, A, B, bm, bn, M, N, K, 16, tid);

#pragma unroll 1
    for (int t = 0; t < nt; t++) {
        if (t + 1 < nt)
            asm volatile("cp.async.wait_group 1;" ::: "memory");
        else
            asm volatile("cp.async.wait_group 0;" ::: "memory");
        __syncthreads();

        if (t + 2 < nt)
            gemm_issue_tile(Asb, Bsb, (t + 2) % GSTAGES, A, B, bm, bn, M, N, K,
                            (t + 2) * 16, tid);

        float* As = Asb + (t % GSTAGES) * 256 * AS_STRIDE;
        float* Bs = Bsb + (t % GSTAGES) * 16 * BS_STRIDE;
#pragma unroll
        for (int ks = 0; ks < 2; ks++) {
            int k0 = ks * 8;
            unsigned af[4][4];
#pragma unroll
            for (int mi = 0; mi < 4; mi++) {
                int m0 = warp_m * 64 + mi * 16 + gr;
                af[mi][0] = __float_as_uint(As[m0 * AS_STRIDE + k0 + gc]);
                af[mi][1] = __float_as_uint(As[(m0 + 8) * AS_STRIDE + k0 + gc]);
                af[mi][2] = __float_as_uint(As[m0 * AS_STRIDE + k0 + gc + 4]);
                af[mi][3] = __float_as_uint(As[(m0 + 8) * AS_STRIDE + k0 + gc + 4]);
            }
            unsigned bf[8][2];
#pragma unroll
            for (int ni = 0; ni < 8; ni++) {
                int n0 = warp_n * 64 + ni * 8 + gr;
                bf[ni][0] = __float_as_uint(Bs[(k0 + gc) * BS_STRIDE + n0]);
                bf[ni][1] = __float_as_uint(Bs[(k0 + gc + 4) * BS_STRIDE + n0]);
            }
#pragma unroll
            for (int mi = 0; mi < 4; mi++)
#pragma unroll
                for (int ni = 0; ni < 8; ni++) {
                    asm volatile(
                        "mma.sync.aligned.m16n8k8.row.col.f32.tf32.tf32.f32 "
                        "{%0,%1,%2,%3}, {%4,%5,%6,%7}, {%8,%9}, {%0,%1,%2,%3};"
                        : "+f"(acc[mi][ni][0]), "+f"(acc[mi][ni][1]),
                          "+f"(acc[mi][ni][2]), "+f"(acc[mi][ni][3])
                        : "r"(af[mi][0]), "r"(af[mi][1]), "r"(af[mi][2]), "r"(af[mi][3]),
                          "r"(bf[ni][0]), "r"(bf[ni][1]));
                }
        }
        __syncthreads();
    }

#pragma unroll
    for (int mi = 0; mi < 4; mi++) {
#pragma unroll
        for (int ni = 0; ni < 8; ni++) {
            int r0 = bm + warp_m * 64 + mi * 16 + gr;
            int cn = bn + warp_n * 64 + ni * 8 + gc * 2;
            if (r0 < M) {
                float2 v = make_float2(acc[mi][ni][0], acc[mi][ni][1]);
                *(float2*)(C + (size_t)r0 * N + cn) = v;
            }
            if (r0 + 8 < M) {
                float2 v = make_float2(acc[mi][ni][2], acc[mi][ni][3]);
                *(float2*)(C + (size_t)(r0 + 8) * N + cn) = v;
            }
        }
    }
}

// ---------------- multi-relation attention dots ----------------
__global__ void k_dots3(const float* __restrict__ Z, int zs4,
                        const float* __restrict__ al, const float* __restrict__ ar,
                        int nrel,
                        float* __restrict__ el0, float* __restrict__ er0,
                        float* __restrict__ el1, float* __restrict__ er1,
                        float* __restrict__ el2, float* __restrict__ er2,
                        int Nn)
{
    int w = (blockIdx.x * blockDim.x + threadIdx.x) >> 5;
    int lane = threadIdx.x & 31;
    if (w >= Nn) return;
    const float4* zp = (const float4*)Z + (size_t)w * zs4;
    const float4* alp = (const float4*)al;
    const float4* arp = (const float4*)ar;

    for (int r = 0; r < nrel; r++) {
        float sl[4], sr[4];
#pragma unroll
        for (int i = 0; i < 4; i++) {
            float4 z = zp[r * 128 + i * 32 + lane];
            float4 a = alp[r * 128 + i * 32 + lane];
            float4 b = arp[r * 128 + i * 32 + lane];
            sl[i] = z.x * a.x + z.y * a.y + z.z * a.z + z.w * a.w;
            sr[i] = z.x * b.x + z.y * b.y + z.z * b.z + z.w * b.w;
        }
#pragma unroll
        for (int o = 16; o > 0; o >>= 1) {
#pragma unroll
            for (int i = 0; i < 4; i++) {
                sl[i] += __shfl_down_sync(0xffffffffu, sl[i], o);
                sr[i] += __shfl_down_sync(0xffffffffu, sr[i], o);
            }
        }
        if (lane == 0) {
            float* el = (r == 0) ? el0 : (r == 1) ? el1 : el2;
            float* er = (r == 0) ? er0 : (r == 1) ? er1 : er2;
#pragma unroll
            for (int i = 0; i < 4; i++) {
                el[w * 4 + i] = sl[i];
                er[w * 4 + i] = sr[i];
            }
        }
    }
}

// ---------------- fused GAT aggregation ----------------
__device__ __forceinline__ float leaky02(float v) { return v > 0.f ? v : 0.2f * v; }

__device__ __forceinline__ void gat_side(
    const int* __restrict__ off, const int* __restrict__ eid,
    const int* __restrict__ src,
    const float* __restrict__ el, float4 r4,
    const float* __restrict__ Z, int zs4,
    int w, int lane, float4 accv[4])
{
    int beg = off[w], end = off[w + 1];
    if (beg >= end) return;

    float m[4] = {-1e30f, -1e30f, -1e30f, -1e30f};
    for (int i = beg + lane; i < end; i += 32) {
        int sn = src[eid[i]];
        float4 e4 = ((const float4*)el)[sn];
        m[0] = fmaxf(m[0], leaky02(e4.x + r4.x));
        m[1] = fmaxf(m[1], leaky02(e4.y + r4.y));
        m[2] = fmaxf(m[2], leaky02(e4.z + r4.z));
        m[3] = fmaxf(m[3], leaky02(e4.w + r4.w));
    }
#pragma unroll
    for (int o = 16; o > 0; o >>= 1) {
#pragma unroll
        for (int k = 0; k < 4; k++)
            m[k] = fmaxf(m[k], __shfl_xor_sync(0xffffffffu, m[k], o));
    }

    float s[4] = {0.f, 0.f, 0.f, 0.f};
    for (int i = beg + lane; i < end; i += 32) {
        int sn = src[eid[i]];
        float4 e4 = ((const float4*)el)[sn];
        s[0] += expf(leaky02(e4.x + r4.x) - m[0]);
        s[1] += expf(leaky02(e4.y + r4.y) - m[1]);
        s[2] += expf(leaky02(e4.z + r4.z) - m[2]);
        s[3] += expf(leaky02(e4.w + r4.w) - m[3]);
    }
#pragma unroll
    for (int o = 16; o > 0; o >>= 1) {
#pragma unroll
        for (int k = 0; k < 4; k++)
            s[k] += __shfl_xor_sync(0xffffffffu, s[k], o);
    }
    float inv[4];
#pragma unroll
    for (int k = 0; k < 4; k++) inv[k] = 1.0f / (s[k] + 1e-9f);

    for (int i = beg; i < end; i++) {
        int sn = src[eid[i]];
        float4 e4 = ((const float4*)el)[sn];
        float a0 = expf(leaky02(e4.x + r4.x) - m[0]) * inv[0];
        float a1 = expf(leaky02(e4.y + r4.y) - m[1]) * inv[1];
        float a2 = expf(leaky02(e4.z + r4.z) - m[2]) * inv[2];
        float a3 = expf(leaky02(e4.w + r4.w) - m[3]) * inv[3];
        const float4* zp = (const float4*)Z + (size_t)sn * zs4;
        float4 z0 = zp[0 * 32 + lane];
        float4 z1 = zp[1 * 32 + lane];
        float4 z2 = zp[2 * 32 + lane];
        float4 z3 = zp[3 * 32 + lane];
        accv[0].x += a0 * z0.x; accv[0].y += a0 * z0.y;
        accv[0].z += a0 * z0.z; accv[0].w += a0 * z0.w;
        accv[1].x += a1 * z1.x; accv[1].y += a1 * z1.y;
        accv[1].z += a1 * z1.z; accv[1].w += a1 * z1.w;
        accv[2].x += a2 * z2.x; accv[2].y += a2 * z2.y;
        accv[2].z += a2 * z2.z; accv[2].w += a2 * z2.w;
        accv[3].x += a3 * z3.x; accv[3].y += a3 * z3.y;
        accv[3].z += a3 * z3.z; accv[3].w += a3 * z3.w;
    }
}

// merged paper GAT: cites (from ZP) + writes (from ZA) into OP, relu+round, one store
__global__ void k_gat_paper(
    const int* __restrict__ offc, const int* __restrict__ eidc, const int* __restrict__ csrc,
    const float* __restrict__ elc, const float* __restrict__ erc,
    const float* __restrict__ ZP, int zp4,
    const int* __restrict__ offw, const int* __restrict__ eidw, const int* __restrict__ wsrc,
    const float* __restrict__ elw, const float* __restrict__ erw,
    const float* __restrict__ ZA, int za4,
    float* __restrict__ out, int nDst, int dorelu)
{
    int w = (blockIdx.x * blockDim.x + threadIdx.x) >> 5;
    if (w >= nDst) return;
    int lane = threadIdx.x & 31;

    float4 accv[4];
#pragma unroll
    for (int j = 0; j < 4; j++) accv[j] = make_float4(0.f, 0.f, 0.f, 0.f);

    gat_side(offc, eidc, csrc, elc, ((const float4*)erc)[w], ZP, zp4, w, lane, accv);
    gat_side(offw, eidw, wsrc, elw, ((const float4*)erw)[w], ZA, za4, w, lane, accv);

#pragma unroll
    for (int j = 0; j < 4; j++) {
        if (dorelu) {
            accv[j].x = fmaxf(accv[j].x, 0.f);
            accv[j].y = fmaxf(accv[j].y, 0.f);
            accv[j].z = fmaxf(accv[j].z, 0.f);
            accv[j].w = fmaxf(accv[j].w, 0.f);
        }
        accv[j].x = rna_tf32(accv[j].x);
        accv[j].y = rna_tf32(accv[j].y);
        accv[j].z = rna_tf32(accv[j].z);
        accv[j].w = rna_tf32(accv[j].w);
    }
    float4* op = (float4*)out + (size_t)w * 128;
#pragma unroll
    for (int j = 0; j < 4; j++) op[j * 32 + lane] = accv[j];
}

// single-relation GAT (authors, wb)
__global__ void k_gat_single(
    const int* __restrict__ off, const int* __restrict__ eid, const int* __restrict__ src,
    const float* __restrict__ el, const float* __restrict__ er,
    const float* __restrict__ Z, int zs4,
    float* __restrict__ out, int nDst, int dorelu)
{
    int w = (blockIdx.x * blockDim.x + threadIdx.x) >> 5;
    if (w >= nDst) return;
    int lane = threadIdx.x & 31;

    float4 accv[4];
#pragma unroll
    for (int j = 0; j < 4; j++) accv[j] = make_float4(0.f, 0.f, 0.f, 0.f);

    gat_side(off, eid, src, el, ((const float4*)er)[w], Z, zs4, w, lane, accv);

#pragma unroll
    for (int j = 0; j < 4; j++) {
        if (dorelu) {
            accv[j].x = fmaxf(accv[j].x, 0.f);
            accv[j].y = fmaxf(accv[j].y, 0.f);
            accv[j].z = fmaxf(accv[j].z, 0.f);
            accv[j].w = fmaxf(accv[j].w, 0.f);
        }
        accv[j].x = rna_tf32(accv[j].x);
        accv[j].y = rna_tf32(accv[j].y);
        accv[j].z = rna_tf32(accv[j].z);
        accv[j].w = rna_tf32(accv[j].w);
    }
    float4* op = (float4*)out + (size_t)w * 128;
#pragma unroll
    for (int j = 0; j < 4; j++) op[j * 32 + lane] = accv[j];
}

// ---------------- host-side launch helpers ----------------
static inline void launch_gemm_tf32(const float* A, const float* B, float* C,
                                    int M, int N, int K)
{
    dim3 grid(N / 128, (M + 255) / 256);
    k_tf32_gemm<<<grid, 256, SMEM_GEMM>>>(A, B, C, M, N, K);
}

static inline void launch_cvt(const float* in, float* out, size_t n)
{
    int n4 = (int)(n / 4);
    int blocks = (n4 + 255) / 256;
    if (blocks > 2048) blocks = 2048;
    k_cvt_tf32<<<blocks, 256>>>(in, out, n4);
}

static inline void build_csr(const int* dst, int E, int nDst,
                             int* cnt, int* off, int* eid)
{
    k_izero<<<(nDst + 255) / 256, 256>>>(cnt, nDst);
    k_hist<<<(E + 255) / 256, 256>>>(dst, E, cnt);
    k_scan<<<1, 1024>>>(cnt, off, nDst);
    k_izero<<<(nDst + 255) / 256, 256>>>(cnt, nDst);
    k_scatter<<<(E + 255) / 256, 256>>>(dst, E, off, cnt, eid);
}

static inline void launch_pack_w(const float* W, float* out, int K, int r0, int nrel)
{
    int total = K * nrel * 128;
    int blocks = (total + 255) / 256;
    if (blocks > 2048) blocks = 2048;
    k_pack_w<<<blocks, 256>>>(W, out, K, r0, nrel);
}

extern "C" void kernel_launch(void* const* d_in, const int* in_sizes, int n_in,
                              void* d_out, int out_size)
{
    const float* x_paper  = (const float*)d_in[0];
    const float* x_author = (const float*)d_in[1];
    const int* cs = (const int*)d_in[2];
    const int* cd = (const int*)d_in[3];
    const int* ws = (const int*)d_in[4];
    const int* wd = (const int*)d_in[5];
    const int* bsrc = (const int*)d_in[6];
    const int* bdst = (const int*)d_in[7];
    const float* Wt[3] = { (const float*)d_in[8],  (const float*)d_in[11], (const float*)d_in[14] };
    const float* AL[3] = { (const float*)d_in[9],  (const float*)d_in[12], (const float*)d_in[15] };
    const float* AR[3] = { (const float*)d_in[10], (const float*)d_in[13], (const float*)d_in[16] };
    const float* linW = (const float*)d_in[17];
    const float* linb = (const float*)d_in[18];
    float* out = (float*)d_out;

    cudaFuncSetAttribute(k_tf32_gemm, cudaFuncAttributeMaxDynamicSharedMemorySize, SMEM_GEMM);

    float *ZP, *ZA, *OP, *OA, *Ap, *Aa, *Wp, *Wa, *lin;
    float *elc, *erc, *elw, *erw, *elb, *erb, *jp, *ja;
    int *cnt, *offc, *offw, *offb, *eidc, *eidw, *eidb;
    cudaGetSymbolAddress((void**)&ZP,  g_ZP);
    cudaGetSymbolAddress((void**)&ZA,  g_ZA);
    cudaGetSymbolAddress((void**)&OP,  g_OP);
    cudaGetSymbolAddress((void**)&OA,  g_OA);
    cudaGetSymbolAddress((void**)&Ap,  g_Ap);
    cudaGetSymbolAddress((void**)&Aa,  g_Aa);
    cudaGetSymbolAddress((void**)&Wp,  g_Wp);
    cudaGetSymbolAddress((void**)&Wa,  g_Wa);
    cudaGetSymbolAddress((void**)&lin, g_lin);
    cudaGetSymbolAddress((void**)&elc, g_elc);
    cudaGetSymbolAddress((void**)&erc, g_erc);
    cudaGetSymbolAddress((void**)&elw, g_elw);
    cudaGetSymbolAddress((void**)&erw, g_erw);
    cudaGetSymbolAddress((void**)&elb, g_elb);
    cudaGetSymbolAddress((void**)&erb, g_erb);
    cudaGetSymbolAddress((void**)&jp,  g_jp);
    cudaGetSymbolAddress((void**)&ja,  g_ja);
    cudaGetSymbolAddress((void**)&cnt,  g_cnt);
    cudaGetSymbolAddress((void**)&offc, g_offc);
    cudaGetSymbolAddress((void**)&offw, g_offw);
    cudaGetSymbolAddress((void**)&offb, g_offb);
    cudaGetSymbolAddress((void**)&eidc, g_eidc);
    cudaGetSymbolAddress((void**)&eidw, g_eidw);
    cudaGetSymbolAddress((void**)&eidb, g_eidb);

    // layer-0 activation conversion first (also: puts GEMMs early so ncu -s 5 captures one)
    launch_cvt(x_paper,  Ap, (size_t)NPAPER * 1024);
    launch_cvt(x_author, Aa, (size_t)NAUTH * 1024);

    for (int L = 0; L < 3; ++L) {
        const float* hp = (L == 0) ? Ap : OP;
        const float* ha = (L == 0) ? Aa : OA;
        int K = (L == 0) ? 1024 : 512;
        const float* al = AL[L];
        const float* ar = AR[L];
        int relu = (L < 2) ? 1 : 0;
        int last = (L == 2);

        int nrp = last ? 2 : 3;
        int nra = last ? 1 : 2;
        int Np = nrp * 512, Na = nra * 512;
        launch_pack_w(Wt[L], Wp, K, 0, nrp);
        launch_pack_w(Wt[L], Wa, K, 1, nra);

        launch_gemm_tf32(hp, Wp, ZP, NPAPER, Np, K);
        launch_gemm_tf32(ha, Wa, ZA, NAUTH, Na, K);

        // CSR build (stream-ordered before first GAT use; placed after first GEMMs
        // so the ncu skip-window lands on a GEMM launch)
        if (L == 0) {
            build_csr(cd,   NEC,  NPAPER, cnt, offc, eidc);
            build_csr(wd,   NEW_, NPAPER, cnt, offw, eidw);
            build_csr(bdst, NEB,  NAUTH,  cnt, offb, eidb);
        }

        int zp4 = Np / 4, za4 = Na / 4;

        // attention logits
        {
            int thr = NPAPER * 32;
            k_dots3<<<(thr + 255) / 256, 256>>>(ZP, zp4, al, ar, nrp,
                                                elc, erc, jp, erw, elb, jp, NPAPER);
        }
        {
            int thr = NAUTH * 32;
            k_dots3<<<(thr + 255) / 256, 256>>>(ZA, za4, al + 512, ar + 512, nra,
                                                elw, ja, ja, erb, ja, ja, NAUTH);
        }

        // merged paper aggregation (cites + writes), fused relu + tf32 round
        {
            int thr = NPAPER * 32;
            k_gat_paper<<<(thr + 255) / 256, 256>>>(
                offc, eidc, cs, elc, erc, ZP, zp4,
                offw, eidw, ws, elw, erw, ZA, za4,
                OP, NPAPER, relu);
        }
        // author aggregation (wb) — not needed in last layer
        if (!last) {
            int thr = NAUTH * 32;
            k_gat_single<<<(thr + 255) / 256, 256>>>(
                offb, eidb, bsrc, elb, erb, ZP + 1024, zp4, OA, NAUTH, relu);
        }
    }

    // classifier: tf32 GEMM into padded scratch, then bias + copy-out
    k_pack_lin<<<(512 * 256 + 255) / 256, 256>>>(linW, lin);
    launch_gemm_tf32(OP, lin, Ap, NPAPER, 256, HIDDEN);
    {
        int total = NPAPER * NCLS;
        int blocks = (total + 255) / 256;
        if (blocks > 4096) blocks = 4096;
        k_bias_out<<<blocks, 256>>>(Ap, linb, out, NPAPER);
    }
}

// round 12
// speedup vs baseline: 1.1559x; 1.1559x over previous
#include <cuda_runtime.h>
#include <cstdint>

#define NPAPER 60000
#define NAUTH  30000
#define NEC    300000
#define NEW_   150000
#define NEB    150000
#define HIDDEN 512
#define NCLS   153

// ---------------- scratch (device globals; no allocation allowed) ----------------
__device__ float g_ZP [(size_t)NPAPER * 1536];
__device__ float g_ZA [(size_t)NAUTH  * 1024];
__device__ float g_OP [(size_t)NPAPER * HIDDEN];
__device__ float g_OA [(size_t)NAUTH * HIDDEN];
__device__ float g_Ap [(size_t)NPAPER * 1024];   // tf32 layer-0 paper feats / classifier scratch
__device__ float g_Aa [(size_t)NAUTH  * 1024];
__device__ float g_Wp [(size_t)1024 * 1536];
__device__ float g_Wa [(size_t)1024 * 1024];
__device__ float g_lin[512 * 256];
__device__ float g_elc[NPAPER * 4];
__device__ float g_erc[NPAPER * 4];
__device__ float g_elw[NAUTH  * 4];
__device__ float g_erw[NPAPER * 4];
__device__ float g_elb[NPAPER * 4];
__device__ float g_erb[NAUTH  * 4];
__device__ float g_jp [NPAPER * 4];
__device__ float g_ja [NAUTH  * 4];
// CSR scratch
__device__ int g_cnt [NPAPER];
__device__ int g_offc[NPAPER + 1];
__device__ int g_offw[NPAPER + 1];
__device__ int g_offb[NAUTH + 1];
__device__ int g_eidc[NEC];
__device__ int g_eidw[NEW_];
__device__ int g_eidb[NEB];

// ---------------- helpers ----------------
__device__ __forceinline__ float rna_tf32(float f) {
    unsigned u;
    asm("cvt.rna.tf32.f32 %0, %1;" : "=r"(u) : "f"(f));
    return __uint_as_float(u);
}

__global__ void k_izero(int* __restrict__ p, int n) {
    int i = blockIdx.x * blockDim.x + threadIdx.x;
    int stride = gridDim.x * blockDim.x;
    for (; i < n; i += stride) p[i] = 0;
}

__global__ void k_cvt_tf32(const float* __restrict__ in, float* __restrict__ out, int n4) {
    int i = blockIdx.x * blockDim.x + threadIdx.x;
    int stride = gridDim.x * blockDim.x;
    for (; i < n4; i += stride) {
        float4 v = ((const float4*)in)[i];
        v.x = rna_tf32(v.x); v.y = rna_tf32(v.y);
        v.z = rna_tf32(v.z); v.w = rna_tf32(v.w);
        ((float4*)out)[i] = v;
    }
}

// pack weights W[(3,K,512)] relations [r0, r0+nrel) -> out[k][(q*512)+n], tf32
__global__ void k_pack_w(const float* __restrict__ W, float* __restrict__ out,
                         int K, int r0, int nrel) {
    int total = K * nrel * 128;
    int i = blockIdx.x * blockDim.x + threadIdx.x;
    int stride = gridDim.x * blockDim.x;
    for (; i < total; i += stride) {
        int n4 = i & 127;
        int kq = i >> 7;
        int q = kq % nrel, k = kq / nrel;
        float4 v = ((const float4*)(W + ((size_t)(r0 + q) * K + k) * 512))[n4];
        v.x = rna_tf32(v.x); v.y = rna_tf32(v.y);
        v.z = rna_tf32(v.z); v.w = rna_tf32(v.w);
        ((float4*)(out + ((size_t)k * nrel + q) * 512))[n4] = v;
    }
}

__global__ void k_pack_lin(const float* __restrict__ linW, float* __restrict__ out) {
    int i = blockIdx.x * blockDim.x + threadIdx.x;
    if (i >= 512 * 256) return;
    int k = i >> 8, c = i & 255;
    out[i] = (c < NCLS) ? rna_tf32(linW[k * NCLS + c]) : 0.0f;
}

__global__ void k_bias_out(const float* __restrict__ CO, const float* __restrict__ bias,
                           float* __restrict__ out, int M) {
    int i = blockIdx.x * blockDim.x + threadIdx.x;
    int stride = gridDim.x * blockDim.x;
    int total = M * NCLS;
    for (; i < total; i += stride) {
        int r = i / NCLS, c = i - r * NCLS;
        out[i] = CO[(size_t)r * 256 + c] + bias[c];
    }
}

// ---------------- CSR build ----------------
__global__ void k_hist(const int* __restrict__ dst, int E, int* __restrict__ cnt) {
    int e = blockIdx.x * blockDim.x + threadIdx.x;
    if (e < E) atomicAdd(&cnt[dst[e]], 1);
}

__global__ void k_scan(const int* __restrict__ cnt, int* __restrict__ off, int n) {
    __shared__ int sh[1024];
    int tid = threadIdx.x;
    int C = (n + 1023) / 1024;
    int b = tid * C;
    int sum = 0;
    for (int i = 0; i < C; i++)
        if (b + i < n) sum += cnt[b + i];
    sh[tid] = sum;
    __syncthreads();
    for (int d = 1; d < 1024; d <<= 1) {
        int t = 0;
        if (tid >= d) t = sh[tid - d];
        __syncthreads();
        if (tid >= d) sh[tid] += t;
        __syncthreads();
    }
    int run = sh[tid] - sum;
    for (int i = 0; i < C; i++) {
        if (b + i < n) { off[b + i] = run; run += cnt[b + i]; }
    }
    if (tid == 1023) off[n] = sh[1023];
}

__global__ void k_scatter(const int* __restrict__ dst, int E,
                          const int* __restrict__ off, int* __restrict__ cur,
                          int* __restrict__ eid) {
    int e = blockIdx.x * blockDim.x + threadIdx.x;
    if (e >= E) return;
    int d = dst[e];
    int p = off[d] + atomicAdd(&cur[d], 1);
    eid[p] = e;
}

// ---------------- TF32 tensor-core GEMM, 128x128 tile, 3-stage cp.async ----------------
// C[M,N] = A[M,K] @ B[K,N], row-major, N % 128 == 0, K % 16 == 0, inputs tf32-rounded.
// Optional fused attention-dot epilogue: each 128-col block tile is one
// (relation q = bn>>9, head h = (bn&511)>>7) slice; computes
// el[row,h] += sum_d acc*al[q,h,d], er likewise, via 4-lane reduce + atomicAdd.
#define AS_STRIDE 20
#define BS_STRIDE 136
#define GSTAGES 3
#define SMEM_GEMM ((GSTAGES * 128 * AS_STRIDE + GSTAGES * 16 * BS_STRIDE) * 4)

__device__ __forceinline__ uint32_t smem_u32(const void* p) {
    uint32_t a;
    asm("{ .reg .u64 t; cvta.to.shared.u64 t, %1; cvt.u32.u64 %0, t; }" : "=r"(a) : "l"(p));
    return a;
}

__device__ __forceinline__ void cp16(uint32_t s, const float* g, bool v) {
    asm volatile("cp.async.cg.shared.global [%0], [%1], 16, %2;"
                 :: "r"(s), "l"(__cvta_generic_to_global(g)), "r"(v ? 16 : 0));
}

__device__ __forceinline__ void gemm_issue_tile(
    float* Asb, float* Bsb, int s,
    const float* __restrict__ A, const float* __restrict__ B,
    int bm, int bn, int M, int N, int K, int k0, int tid)
{
    int am = tid >> 2, ac4 = tid & 3;
    int bk = tid >> 5, bc4 = tid & 31;
    float* As = Asb + s * 128 * AS_STRIDE;
    float* Bs = Bsb + s * 16 * BS_STRIDE;
#pragma unroll
    for (int i = 0; i < 2; i++) {
        int m = am + i * 64;
        int mm = bm + m;
        int msafe = mm < M ? mm : (M - 1);
        cp16(smem_u32(As + m * AS_STRIDE + ac4 * 4),
             A + (size_t)msafe * K + k0 + ac4 * 4, mm < M);
    }
#pragma unroll
    for (int i = 0; i < 2; i++) {
        int kr = bk + i * 8;
        cp16(smem_u32(Bs + kr * BS_STRIDE + bc4 * 4),
             B + (size_t)(k0 + kr) * N + bn + bc4 * 4, true);
    }
    asm volatile("cp.async.commit_group;" ::: "memory");
}

__global__ __launch_bounds__(256) void k_tf32_gemm(
    const float* __restrict__ A, const float* __restrict__ B,
    float* __restrict__ C, int M, int N, int K,
    const float* __restrict__ al, const float* __restrict__ ar,
    float* el0, float* er0, float* el1, float* er1, float* el2, float* er2,
    int dofuse)
{
    extern __shared__ float sm[];
    float* Asb = sm;
    float* Bsb = sm + GSTAGES * 128 * AS_STRIDE;

    int tid = threadIdx.x;
    int lane = tid & 31;
    int wid = tid >> 5;
    int warp_m = wid & 3;
    int warp_n = wid >> 2;
    int gr = lane >> 2;
    int gc = lane & 3;

    int bm = blockIdx.y * 128;
    int bn = blockIdx.x * 128;

    float acc[2][8][4];
#pragma unroll
    for (int mi = 0; mi < 2; mi++)
#pragma unroll
        for (int ni = 0; ni < 8; ni++)
#pragma unroll
            for (int j = 0; j < 4; j++) acc[mi][ni][j] = 0.0f;

    int nt = K >> 4;

    gemm_issue_tile(Asb, Bsb, 0, A, B, bm, bn, M, N, K, 0, tid);
    if (nt > 1)
        gemm_issue_tile(Asb, Bsb, 1, A, B, bm, bn, M, N, K, 16, tid);

#pragma unroll 1
    for (int t = 0; t < nt; t++) {
        if (t + 1 < nt)
            asm volatile("cp.async.wait_group 1;" ::: "memory");
        else
            asm volatile("cp.async.wait_group 0;" ::: "memory");
        __syncthreads();

        if (t + 2 < nt)
            gemm_issue_tile(Asb, Bsb, (t + 2) % GSTAGES, A, B, bm, bn, M, N, K,
                            (t + 2) * 16, tid);

        float* As = Asb + (t % GSTAGES) * 128 * AS_STRIDE;
        float* Bs = Bsb + (t % GSTAGES) * 16 * BS_STRIDE;
#pragma unroll
        for (int ks = 0; ks < 2; ks++) {
            int k0 = ks * 8;
            unsigned af[2][4];
#pragma unroll
            for (int mi = 0; mi < 2; mi++) {
                int m0 = warp_m * 32 + mi * 16 + gr;
                af[mi][0] = __float_as_uint(As[m0 * AS_STRIDE + k0 + gc]);
                af[mi][1] = __float_as_uint(As[(m0 + 8) * AS_STRIDE + k0 + gc]);
                af[mi][2] = __float_as_uint(As[m0 * AS_STRIDE + k0 + gc + 4]);
                af[mi][3] = __float_as_uint(As[(m0 + 8) * AS_STRIDE + k0 + gc + 4]);
            }
            unsigned bf[8][2];
#pragma unroll
            for (int ni = 0; ni < 8; ni++) {
                int n0 = warp_n * 64 + ni * 8 + gr;
                bf[ni][0] = __float_as_uint(Bs[(k0 + gc) * BS_STRIDE + n0]);
                bf[ni][1] = __float_as_uint(Bs[(k0 + gc + 4) * BS_STRIDE + n0]);
            }
#pragma unroll
            for (int mi = 0; mi < 2; mi++)
#pragma unroll
                for (int ni = 0; ni < 8; ni++) {
                    asm volatile(
                        "mma.sync.aligned.m16n8k8.row.col.f32.tf32.tf32.f32 "
                        "{%0,%1,%2,%3}, {%4,%5,%6,%7}, {%8,%9}, {%0,%1,%2,%3};"
                        : "+f"(acc[mi][ni][0]), "+f"(acc[mi][ni][1]),
                          "+f"(acc[mi][ni][2]), "+f"(acc[mi][ni][3])
                        : "r"(af[mi][0]), "r"(af[mi][1]), "r"(af[mi][2]), "r"(af[mi][3]),
                          "r"(bf[ni][0]), "r"(bf[ni][1]));
                }
        }
        __syncthreads();
    }

    // store C
#pragma unroll
    for (int mi = 0; mi < 2; mi++) {
#pragma unroll
        for (int ni = 0; ni < 8; ni++) {
            int r0 = bm + warp_m * 32 + mi * 16 + gr;
            int cn = bn + warp_n * 64 + ni * 8 + gc * 2;
            if (r0 < M) {
                float2 v = make_float2(acc[mi][ni][0], acc[mi][ni][1]);
                *(float2*)(C + (size_t)r0 * N + cn) = v;
            }
            if (r0 + 8 < M) {
                float2 v = make_float2(acc[mi][ni][2], acc[mi][ni][3]);
                *(float2*)(C + (size_t)(r0 + 8) * N + cn) = v;
            }
        }
    }

    // fused attention-dot epilogue
    if (dofuse) {
        int relq = bn >> 9;
        int h = (bn & 511) >> 7;
        const float* alp = al + (relq << 9) + (h << 7);
        const float* arp = ar + (relq << 9) + (h << 7);
        float* el = (relq == 0) ? el0 : (relq == 1) ? el1 : el2;
        float* er = (relq == 0) ? er0 : (relq == 1) ? er1 : er2;

#pragma unroll
        for (int mi = 0; mi < 2; mi++) {
            float plA = 0.f, prA = 0.f, plB = 0.f, prB = 0.f;
#pragma unroll
            for (int ni = 0; ni < 8; ni++) {
                int d = warp_n * 64 + ni * 8 + gc * 2;
                float a0 = alp[d], a1 = alp[d + 1];
                float b0 = arp[d], b1 = arp[d + 1];
                plA += acc[mi][ni][0] * a0 + acc[mi][ni][1] * a1;
                prA += acc[mi][ni][0] * b0 + acc[mi][ni][1] * b1;
                plB += acc[mi][ni][2] * a0 + acc[mi][ni][3] * a1;
                prB += acc[mi][ni][2] * b0 + acc[mi][ni][3] * b1;
            }
            // reduce across the 4 gc lanes holding this row
            plA += __shfl_xor_sync(0xffffffffu, plA, 1);
            plA += __shfl_xor_sync(0xffffffffu, plA, 2);
            prA += __shfl_xor_sync(0xffffffffu, prA, 1);
            prA += __shfl_xor_sync(0xffffffffu, prA, 2);
            plB += __shfl_xor_sync(0xffffffffu, plB, 1);
            plB += __shfl_xor_sync(0xffffffffu, plB, 2);
            prB += __shfl_xor_sync(0xffffffffu, prB, 1);
            prB += __shfl_xor_sync(0xffffffffu, prB, 2);

            int rA = bm + warp_m * 32 + mi * 16 + gr;
            int rB = rA + 8;
            if (gc == 0) {
                if (rA < M) {
                    atomicAdd(&el[rA * 4 + h], plA);
                    atomicAdd(&er[rA * 4 + h], prA);
                }
                if (rB < M) {
                    atomicAdd(&el[rB * 4 + h], plB);
                    atomicAdd(&er[rB * 4 + h], prB);
                }
            }
        }
    }
}

// ---------------- fused GAT aggregation ----------------
__device__ __forceinline__ float leaky02(float v) { return v > 0.f ? v : 0.2f * v; }

__device__ __forceinline__ void gat_side(
    const int* __restrict__ off, const int* __restrict__ eid,
    const int* __restrict__ src,
    const float* __restrict__ el, float4 r4,
    const float* __restrict__ Z, int zs4,
    int w, int lane, float4 accv[4])
{
    int beg = off[w], end = off[w + 1];
    if (beg >= end) return;

    float m[4] = {-1e30f, -1e30f, -1e30f, -1e30f};
    for (int i = beg + lane; i < end; i += 32) {
        int sn = src[eid[i]];
        float4 e4 = ((const float4*)el)[sn];
        m[0] = fmaxf(m[0], leaky02(e4.x + r4.x));
        m[1] = fmaxf(m[1], leaky02(e4.y + r4.y));
        m[2] = fmaxf(m[2], leaky02(e4.z + r4.z));
        m[3] = fmaxf(m[3], leaky02(e4.w + r4.w));
    }
#pragma unroll
    for (int o = 16; o > 0; o >>= 1) {
#pragma unroll
        for (int k = 0; k < 4; k++)
            m[k] = fmaxf(m[k], __shfl_xor_sync(0xffffffffu, m[k], o));
    }

    float s[4] = {0.f, 0.f, 0.f, 0.f};
    for (int i = beg + lane; i < end; i += 32) {
        int sn = src[eid[i]];
        float4 e4 = ((const float4*)el)[sn];
        s[0] += expf(leaky02(e4.x + r4.x) - m[0]);
        s[1] += expf(leaky02(e4.y + r4.y) - m[1]);
        s[2] += expf(leaky02(e4.z + r4.z) - m[2]);
        s[3] += expf(leaky02(e4.w + r4.w) - m[3]);
    }
#pragma unroll
    for (int o = 16; o > 0; o >>= 1) {
#pragma unroll
        for (int k = 0; k < 4; k++)
            s[k] += __shfl_xor_sync(0xffffffffu, s[k], o);
    }
    float inv[4];
#pragma unroll
    for (int k = 0; k < 4; k++) inv[k] = 1.0f / (s[k] + 1e-9f);

    for (int i = beg; i < end; i++) {
        int sn = src[eid[i]];
        float4 e4 = ((const float4*)el)[sn];
        float a0 = expf(leaky02(e4.x + r4.x) - m[0]) * inv[0];
        float a1 = expf(leaky02(e4.y + r4.y) - m[1]) * inv[1];
        float a2 = expf(leaky02(e4.z + r4.z) - m[2]) * inv[2];
        float a3 = expf(leaky02(e4.w + r4.w) - m[3]) * inv[3];
        const float4* zp = (const float4*)Z + (size_t)sn * zs4;
        float4 z0 = zp[0 * 32 + lane];
        float4 z1 = zp[1 * 32 + lane];
        float4 z2 = zp[2 * 32 + lane];
        float4 z3 = zp[3 * 32 + lane];
        accv[0].x += a0 * z0.x; accv[0].y += a0 * z0.y;
        accv[0].z += a0 * z0.z; accv[0].w += a0 * z0.w;
        accv[1].x += a1 * z1.x; accv[1].y += a1 * z1.y;
        accv[1].z += a1 * z1.z; accv[1].w += a1 * z1.w;
        accv[2].x += a2 * z2.x; accv[2].y += a2 * z2.y;
        accv[2].z += a2 * z2.z; accv[2].w += a2 * z2.w;
        accv[3].x += a3 * z3.x; accv[3].y += a3 * z3.y;
        accv[3].z += a3 * z3.z; accv[3].w += a3 * z3.w;
    }
}

// merged paper GAT: cites (from ZP) + writes (from ZA) into OP, relu+round, one store
__global__ void k_gat_paper(
    const int* __restrict__ offc, const int* __restrict__ eidc, const int* __restrict__ csrc,
    const float* __restrict__ elc, const float* __restrict__ erc,
    const float* __restrict__ ZP, int zp4,
    const int* __restrict__ offw, const int* __restrict__ eidw, const int* __restrict__ wsrc,
    const float* __restrict__ elw, const float* __restrict__ erw,
    const float* __restrict__ ZA, int za4,
    float* __restrict__ out, int nDst, int dorelu)
{
    int w = (blockIdx.x * blockDim.x + threadIdx.x) >> 5;
    if (w >= nDst) return;
    int lane = threadIdx.x & 31;

    float4 accv[4];
#pragma unroll
    for (int j = 0; j < 4; j++) accv[j] = make_float4(0.f, 0.f, 0.f, 0.f);

    gat_side(offc, eidc, csrc, elc, ((const float4*)erc)[w], ZP, zp4, w, lane, accv);
    gat_side(offw, eidw, wsrc, elw, ((const float4*)erw)[w], ZA, za4, w, lane, accv);

#pragma unroll
    for (int j = 0; j < 4; j++) {
        if (dorelu) {
            accv[j].x = fmaxf(accv[j].x, 0.f);
            accv[j].y = fmaxf(accv[j].y, 0.f);
            accv[j].z = fmaxf(accv[j].z, 0.f);
            accv[j].w = fmaxf(accv[j].w, 0.f);
        }
        accv[j].x = rna_tf32(accv[j].x);
        accv[j].y = rna_tf32(accv[j].y);
        accv[j].z = rna_tf32(accv[j].z);
        accv[j].w = rna_tf32(accv[j].w);
    }
    float4* op = (float4*)out + (size_t)w * 128;
#pragma unroll
    for (int j = 0; j < 4; j++) op[j * 32 + lane] = accv[j];
}

// single-relation GAT (authors, wb)
__global__ void k_gat_single(
    const int* __restrict__ off, const int* __restrict__ eid, const int* __restrict__ src,
    const float* __restrict__ el, const float* __restrict__ er,
    const float* __restrict__ Z, int zs4,
    float* __restrict__ out, int nDst, int dorelu)
{
    int w = (blockIdx.x * blockDim.x + threadIdx.x) >> 5;
    if (w >= nDst) return;
    int lane = threadIdx.x & 31;

    float4 accv[4];
#pragma unroll
    for (int j = 0; j < 4; j++) accv[j] = make_float4(0.f, 0.f, 0.f, 0.f);

    gat_side(off, eid, src, el, ((const float4*)er)[w], Z, zs4, w, lane, accv);

#pragma unroll
    for (int j = 0; j < 4; j++) {
        if (dorelu) {
            accv[j].x = fmaxf(accv[j].x, 0.f);
            accv[j].y = fmaxf(accv[j].y, 0.f);
            accv[j].z = fmaxf(accv[j].z, 0.f);
            accv[j].w = fmaxf(accv[j].w, 0.f);
        }
        accv[j].x = rna_tf32(accv[j].x);
        accv[j].y = rna_tf32(accv[j].y);
        accv[j].z = rna_tf32(accv[j].z);
        accv[j].w = rna_tf32(accv[j].w);
    }
    float4* op = (float4*)out + (size_t)w * 128;
#pragma unroll
    for (int j = 0; j < 4; j++) op[j * 32 + lane] = accv[j];
}

// ---------------- host-side launch helpers ----------------
static inline void launch_gemm_fused(const float* A, const float* B, float* C,
                                     int M, int N, int K,
                                     const float* al, const float* ar,
                                     float* el0, float* er0, float* el1, float* er1,
                                     float* el2, float* er2)
{
    dim3 grid(N / 128, (M + 127) / 128);
    k_tf32_gemm<<<grid, 256, SMEM_GEMM>>>(A, B, C, M, N, K, al, ar,
                                          el0, er0, el1, er1, el2, er2, 1);
}

static inline void launch_gemm_plain(const float* A, const float* B, float* C,
                                     int M, int N, int K)
{
    dim3 grid(N / 128, (M + 127) / 128);
    k_tf32_gemm<<<grid, 256, SMEM_GEMM>>>(A, B, C, M, N, K, nullptr, nullptr,
                                          nullptr, nullptr, nullptr, nullptr,
                                          nullptr, nullptr, 0);
}

static inline void launch_cvt(const float* in, float* out, size_t n)
{
    int n4 = (int)(n / 4);
    int blocks = (n4 + 255) / 256;
    if (blocks > 2048) blocks = 2048;
    k_cvt_tf32<<<blocks, 256>>>(in, out, n4);
}

static inline void launch_zero_f(float* p, int n)
{
    int blocks = (n + 255) / 256;
    if (blocks > 2048) blocks = 2048;
    k_izero<<<blocks, 256>>>((int*)p, n);
}

static inline void build_csr(const int* dst, int E, int nDst,
                             int* cnt, int* off, int* eid)
{
    k_izero<<<(nDst + 255) / 256, 256>>>(cnt, nDst);
    k_hist<<<(E + 255) / 256, 256>>>(dst, E, cnt);
    k_scan<<<1, 1024>>>(cnt, off, nDst);
    k_izero<<<(nDst + 255) / 256, 256>>>(cnt, nDst);
    k_scatter<<<(E + 255) / 256, 256>>>(dst, E, off, cnt, eid);
}

static inline void launch_pack_w(const float* W, float* out, int K, int r0, int nrel)
{
    int total = K * nrel * 128;
    int blocks = (total + 255) / 256;
    if (blocks > 2048) blocks = 2048;
    k_pack_w<<<blocks, 256>>>(W, out, K, r0, nrel);
}

extern "C" void kernel_launch(void* const* d_in, const int* in_sizes, int n_in,
                              void* d_out, int out_size)
{
    const float* x_paper  = (const float*)d_in[0];
    const float* x_author = (const float*)d_in[1];
    const int* cs = (const int*)d_in[2];
    const int* cd = (const int*)d_in[3];
    const int* ws = (const int*)d_in[4];
    const int* wd = (const int*)d_in[5];
    const int* bsrc = (const int*)d_in[6];
    const int* bdst = (const int*)d_in[7];
    const float* Wt[3] = { (const float*)d_in[8],  (const float*)d_in[11], (const float*)d_in[14] };
    const float* AL[3] = { (const float*)d_in[9],  (const float*)d_in[12], (const float*)d_in[15] };
    const float* AR[3] = { (const float*)d_in[10], (const float*)d_in[13], (const float*)d_in[16] };
    const float* linW = (const float*)d_in[17];
    const float* linb = (const float*)d_in[18];
    float* out = (float*)d_out;

    cudaFuncSetAttribute(k_tf32_gemm, cudaFuncAttributeMaxDynamicSharedMemorySize, SMEM_GEMM);

    float *ZP, *ZA, *OP, *OA, *Ap, *Aa, *Wp, *Wa, *lin;
    float *elc, *erc, *elw, *erw, *elb, *erb, *jp, *ja;
    int *cnt, *offc, *offw, *offb, *eidc, *eidw, *eidb;
    cudaGetSymbolAddress((void**)&ZP,  g_ZP);
    cudaGetSymbolAddress((void**)&ZA,  g_ZA);
    cudaGetSymbolAddress((void**)&OP,  g_OP);
    cudaGetSymbolAddress((void**)&OA,  g_OA);
    cudaGetSymbolAddress((void**)&Ap,  g_Ap);
    cudaGetSymbolAddress((void**)&Aa,  g_Aa);
    cudaGetSymbolAddress((void**)&Wp,  g_Wp);
    cudaGetSymbolAddress((void**)&Wa,  g_Wa);
    cudaGetSymbolAddress((void**)&lin, g_lin);
    cudaGetSymbolAddress((void**)&elc, g_elc);
    cudaGetSymbolAddress((void**)&erc, g_erc);
    cudaGetSymbolAddress((void**)&elw, g_elw);
    cudaGetSymbolAddress((void**)&erw, g_erw);
    cudaGetSymbolAddress((void**)&elb, g_elb);
    cudaGetSymbolAddress((void**)&erb, g_erb);
    cudaGetSymbolAddress((void**)&jp,  g_jp);
    cudaGetSymbolAddress((void**)&ja,  g_ja);
    cudaGetSymbolAddress((void**)&cnt,  g_cnt);
    cudaGetSymbolAddress((void**)&offc, g_offc);
    cudaGetSymbolAddress((void**)&offw, g_offw);
    cudaGetSymbolAddress((void**)&offb, g_offb);
    cudaGetSymbolAddress((void**)&eidc, g_eidc);
    cudaGetSymbolAddress((void**)&eidw, g_eidw);
    cudaGetSymbolAddress((void**)&eidb, g_eidb);

    // layer-0 activation conversion
    launch_cvt(x_paper,  Ap, (size_t)NPAPER * 1024);
    launch_cvt(x_author, Aa, (size_t)NAUTH * 1024);

    for (int L = 0; L < 3; ++L) {
        const float* hp = (L == 0) ? Ap : OP;
        const float* ha = (L == 0) ? Aa : OA;
        int K = (L == 0) ? 1024 : 512;
        const float* al = AL[L];
        const float* ar = AR[L];
        int relu = (L < 2) ? 1 : 0;
        int last = (L == 2);

        int nrp = last ? 2 : 3;
        int nra = last ? 1 : 2;
        int Np = nrp * 512, Na = nra * 512;
        launch_pack_w(Wt[L], Wp, K, 0, nrp);
        launch_pack_w(Wt[L], Wa, K, 1, nra);

        // zero el/er accumulation targets (atomicAdd in GEMM epilogue)
        launch_zero_f(elc, NPAPER * 4);
        launch_zero_f(erc, NPAPER * 4);
        launch_zero_f(erw, NPAPER * 4);
        launch_zero_f(elb, NPAPER * 4);
        launch_zero_f(jp,  NPAPER * 4);
        launch_zero_f(elw, NAUTH * 4);
        launch_zero_f(erb, NAUTH * 4);
        launch_zero_f(ja,  NAUTH * 4);

        // merged projections with fused attention-dot epilogue
        // papers: q0=cites (el->elc, er->erc), q1=writes-dst (er->erw), q2=wb-src (el->elb)
        launch_gemm_fused(hp, Wp, ZP, NPAPER, Np, K, al, ar,
                          elc, erc, jp, erw, elb, jp);
        // authors: q0=writes-src (el->elw), q1=wb-dst (er->erb); al/ar offset +512 (rel 1)
        launch_gemm_fused(ha, Wa, ZA, NAUTH, Na, K, al + 512, ar + 512,
                          elw, ja, ja, erb, nullptr, nullptr);

        // CSR build (after first GEMMs so ncu -s 5 lands on a GEMM)
        if (L == 0) {
            build_csr(cd,   NEC,  NPAPER, cnt, offc, eidc);
            build_csr(wd,   NEW_, NPAPER, cnt, offw, eidw);
            build_csr(bdst, NEB,  NAUTH,  cnt, offb, eidb);
        }

        int zp4 = Np / 4, za4 = Na / 4;

        // merged paper aggregation (cites + writes), fused relu + tf32 round
        {
            int thr = NPAPER * 32;
            k_gat_paper<<<(thr + 255) / 256, 256>>>(
                offc, eidc, cs, elc, erc, ZP, zp4,
                offw, eidw, ws, elw, erw, ZA, za4,
                OP, NPAPER, relu);
        }
        // author aggregation (wb) — not needed in last layer
        if (!last) {
            int thr = NAUTH * 32;
            k_gat_single<<<(thr + 255) / 256, 256>>>(
                offb, eidb, bsrc, elb, erb, ZP + 1024, zp4, OA, NAUTH, relu);
        }
    }

    // classifier: tf32 GEMM into padded scratch, then bias + copy-out
    k_pack_lin<<<(512 * 256 + 255) / 256, 256>>>(linW, lin);
    launch_gemm_plain(OP, lin, Ap, NPAPER, 256, HIDDEN);
    {
        int total = NPAPER * NCLS;
        int blocks = (total + 255) / 256;
        if (blocks > 4096) blocks = 4096;
        k_bias_out<<<blocks, 256>>>(Ap, linb, out, NPAPER);
    }
}